// round 1
// baseline (speedup 1.0000x reference)
#include <cuda_runtime.h>
#include <math.h>

#define B_   16
#define T_   8
#define C_   2048
#define H_   16
#define D_   128
#define MAXSEQ 4096
#define M_   (B_*T_)      // 128
#define N3_  (3*C_)       // 6144
#define NS   16           // kv splits
#define CHUNK (MAXSEQ/NS) // 256 keys per split

// ---------------- scratch (no allocations allowed) ----------------
__device__ __align__(16) float g_qkv[M_ * N3_];             // 128 x 6144
__device__ __align__(16) float g_pacc[B_*H_ * NS * T_ * D_]; // partial acc
__device__ __align__(16) float g_pm[B_*H_ * NS * T_];
__device__ __align__(16) float g_pl[B_*H_ * NS * T_];
__device__ __align__(16) float g_y[M_ * C_];                 // attention output [B,T,C]

// ---------------- generic SGEMM: C = A[MxK] @ B[KxN] + bias ----------------
// BM=64, BN=32, BK=16, 128 threads, 4x4 micro-tile
__global__ __launch_bounds__(128) void sgemm_bias(
    const float* __restrict__ A, const float* __restrict__ Bm,
    const float* __restrict__ bias, float* __restrict__ Cm,
    int K, int N)
{
    __shared__ float As[16][64];
    __shared__ float Bs[16][32];
    const int tid = threadIdx.x;
    const int m0 = blockIdx.y * 64;
    const int n0 = blockIdx.x * 32;
    const int tm = tid >> 3;   // 0..15 (4 rows each)
    const int tn = tid & 7;    // 0..7  (4 cols each)

    float acc[4][4];
#pragma unroll
    for (int i = 0; i < 4; i++)
#pragma unroll
        for (int j = 0; j < 4; j++) acc[i][j] = 0.f;

    for (int k0 = 0; k0 < K; k0 += 16) {
        // A tile: 64 rows x 16 k, transposed into As[k][m]
#pragma unroll
        for (int i = 0; i < 2; i++) {
            int id = tid + i * 128;             // 0..255
            int r  = id >> 2;                   // 0..63
            int c4 = (id & 3) * 4;              // 0,4,8,12
            float4 v = *(const float4*)(A + (size_t)(m0 + r) * K + k0 + c4);
            As[c4 + 0][r] = v.x; As[c4 + 1][r] = v.y;
            As[c4 + 2][r] = v.z; As[c4 + 3][r] = v.w;
        }
        // B tile: 16 k x 32 n
        {
            int r  = tid >> 3;                  // 0..15
            int c4 = (tid & 7) * 4;             // 0..28
            *(float4*)(&Bs[r][c4]) =
                *(const float4*)(Bm + (size_t)(k0 + r) * N + n0 + c4);
        }
        __syncthreads();
#pragma unroll
        for (int k = 0; k < 16; k++) {
            float4 a = *(const float4*)(&As[k][tm * 4]);
            float4 b = *(const float4*)(&Bs[k][tn * 4]);
            float av[4] = {a.x, a.y, a.z, a.w};
            float bv[4] = {b.x, b.y, b.z, b.w};
#pragma unroll
            for (int i = 0; i < 4; i++)
#pragma unroll
                for (int j = 0; j < 4; j++) acc[i][j] += av[i] * bv[j];
        }
        __syncthreads();
    }
    // epilogue + bias
    float4 bb = *(const float4*)(bias + n0 + tn * 4);
    float bv[4] = {bb.x, bb.y, bb.z, bb.w};
#pragma unroll
    for (int i = 0; i < 4; i++) {
        int m = m0 + tm * 4 + i;
        float4 o;
        o.x = acc[i][0] + bv[0]; o.y = acc[i][1] + bv[1];
        o.z = acc[i][2] + bv[2]; o.w = acc[i][3] + bv[3];
        *(float4*)(Cm + (size_t)m * N + n0 + tn * 4) = o;
    }
}

// ---------------- attention partials (flash-decoding) ----------------
// grid.x = (B*H*NS)/4 = 1024 CTAs, 128 threads (4 warps).
// Each warp handles one (b,h,split). Lane owns one key at a time; Q broadcast
// from shared; no cross-lane score reduction needed.
__global__ __launch_bounds__(128) void attn_partial(
    const float* __restrict__ kc, const float* __restrict__ vc,
    const int* __restrict__ p_start, const int* __restrict__ p_causal)
{
    __shared__ float Qs[T_][D_];
    __shared__ float Ps[4][T_][32];

    const int tid  = threadIdx.x;
    const int w    = tid >> 5;
    const int lane = tid & 31;
    const int bh    = blockIdx.x >> 2;
    const int split = ((blockIdx.x & 3) << 2) | w;
    const int b = bh >> 4, h = bh & 15;

    const int start_pos = *p_start;
    const int causal    = *p_causal;
    const int S = start_pos + T_;
    // fold 1/sqrt(D) and log2(e) into Q
    const float QSCALE = 0.08838834764831845f * 1.4426950408889634f;

    // load + scale Q for this (b,h)
    for (int i = tid; i < T_ * 32; i += 128) {   // 256 float4
        int t = i >> 5, dq = (i & 31) * 4;
        float4 v = *(const float4*)(g_qkv + (size_t)(b * T_ + t) * N3_ + h * D_ + dq);
        v.x *= QSCALE; v.y *= QSCALE; v.z *= QSCALE; v.w *= QSCALE;
        *(float4*)(&Qs[t][dq]) = v;
    }
    __syncthreads();

    float m[T_], l[T_];
    float4 acc[T_];
#pragma unroll
    for (int t = 0; t < T_; t++) {
        m[t] = -INFINITY; l[t] = 0.f;
        acc[t] = make_float4(0.f, 0.f, 0.f, 0.f);
    }

    const int s0 = split * CHUNK;
    const float* kbase = kc + (size_t)bh * MAXSEQ * D_;
    const float* vbase = vc + (size_t)bh * MAXSEQ * D_;

    for (int tile = 0; tile < CHUNK / 32; tile++) {
        const int sb = s0 + tile * 32;
        const int s  = sb + lane;
        const bool valid = (s < S);
        const int sl = valid ? s : (S - 1);
        const float* krow = (sl < start_pos)
            ? (kbase + (size_t)sl * D_)
            : (g_qkv + (size_t)(b * T_ + (sl - start_pos)) * N3_ + C_ + h * D_);

        // -------- phase 1: scores (lane = its own key) --------
        float sc[T_];
#pragma unroll
        for (int t = 0; t < T_; t++) sc[t] = 0.f;
#pragma unroll 4
        for (int dq = 0; dq < 32; dq++) {
            float4 kv = *(const float4*)(krow + dq * 4);
#pragma unroll
            for (int t = 0; t < T_; t++) {
                float4 q = *(const float4*)(&Qs[t][dq * 4]);
                sc[t] += q.x * kv.x + q.y * kv.y + q.z * kv.z + q.w * kv.w;
            }
        }
        if (!valid) {
#pragma unroll
            for (int t = 0; t < T_; t++) sc[t] = -INFINITY;
        }
        if (causal) {
#pragma unroll
            for (int t = 0; t < T_; t++) if (s > t) sc[t] = -INFINITY;
        }

        // -------- online softmax update (base-2 domain) --------
#pragma unroll
        for (int t = 0; t < T_; t++) {
            float mt = sc[t];
#pragma unroll
            for (int o = 16; o; o >>= 1)
                mt = fmaxf(mt, __shfl_xor_sync(0xffffffffu, mt, o));
            float mn = fmaxf(m[t], mt);
            float alpha, pv;
            if (mn == -INFINITY) { alpha = 1.f; pv = 0.f; }
            else { alpha = exp2f(m[t] - mn); pv = exp2f(sc[t] - mn); }
            float ps = pv;
#pragma unroll
            for (int o = 16; o; o >>= 1)
                ps += __shfl_xor_sync(0xffffffffu, ps, o);
            l[t] = l[t] * alpha + ps;
            m[t] = mn;
            acc[t].x *= alpha; acc[t].y *= alpha;
            acc[t].z *= alpha; acc[t].w *= alpha;
            Ps[w][t][lane] = pv;
        }
        __syncwarp();

        // -------- phase 2: P @ V (lane owns 4 dims, coalesced V) --------
#pragma unroll 4
        for (int j = 0; j < 32; j++) {
            int ss = sb + j;
            int ssl = (ss < S) ? ss : (S - 1);
            const float* vrow = (ssl < start_pos)
                ? (vbase + (size_t)ssl * D_)
                : (g_qkv + (size_t)(b * T_ + (ssl - start_pos)) * N3_ + 2 * C_ + h * D_);
            float4 vv = *(const float4*)(vrow + lane * 4);
#pragma unroll
            for (int t = 0; t < T_; t++) {
                float pj = Ps[w][t][j];
                acc[t].x += pj * vv.x; acc[t].y += pj * vv.y;
                acc[t].z += pj * vv.z; acc[t].w += pj * vv.w;
            }
        }
        __syncwarp();
    }

    // -------- write partials --------
    const int pbase = (bh * NS + split) * T_;
#pragma unroll
    for (int t = 0; t < T_; t++) {
        if (lane == 0) { g_pm[pbase + t] = m[t]; g_pl[pbase + t] = l[t]; }
        *(float4*)(g_pacc + (size_t)(pbase + t) * D_ + lane * 4) = acc[t];
    }
}

// ---------------- combine partials -> y[B,T,C] ----------------
__global__ __launch_bounds__(128) void attn_combine()
{
    const int bh = blockIdx.x;          // 0..255
    const int d  = threadIdx.x;         // 0..127
    const int b = bh >> 4, h = bh & 15;
    for (int t = 0; t < T_; t++) {
        float M = -INFINITY;
#pragma unroll
        for (int si = 0; si < NS; si++)
            M = fmaxf(M, g_pm[(bh * NS + si) * T_ + t]);
        float L = 0.f, y = 0.f;
#pragma unroll
        for (int si = 0; si < NS; si++) {
            float ms = g_pm[(bh * NS + si) * T_ + t];
            float ls = g_pl[(bh * NS + si) * T_ + t];
            float wgt = (ms == -INFINITY) ? 0.f : exp2f(ms - M);
            L += wgt * ls;
            y += wgt * g_pacc[(size_t)((bh * NS + si) * T_ + t) * D_ + d];
        }
        g_y[(size_t)(b * T_ + t) * C_ + h * D_ + d] = (L > 0.f) ? (y / L) : 0.f;
    }
}

// ---------------- launch ----------------
extern "C" void kernel_launch(void* const* d_in, const int* in_sizes, int n_in,
                              void* d_out, int out_size)
{
    const float* x      = (const float*)d_in[0];
    const float* kc     = (const float*)d_in[1];
    const float* vc     = (const float*)d_in[2];
    const float* w_attn = (const float*)d_in[3];
    const float* b_attn = (const float*)d_in[4];
    const float* w_proj = (const float*)d_in[5];
    const float* b_proj = (const float*)d_in[6];
    const int*   sp     = (const int*)d_in[7];
    const int*   ic     = (const int*)d_in[8];
    float* out = (float*)d_out;

    float* qkv = nullptr; float* y = nullptr;
    cudaGetSymbolAddress((void**)&qkv, g_qkv);
    cudaGetSymbolAddress((void**)&y,   g_y);

    // 1) QKV projection: [128,2048] @ [2048,6144] + bias
    sgemm_bias<<<dim3(N3_ / 32, M_ / 64), 128>>>(x, w_attn, b_attn, qkv, C_, N3_);

    // 2) attention partials (flash-decoding over 16 splits)
    attn_partial<<<(B_ * H_ * NS) / 4, 128>>>(kc, vc, sp, ic);

    // 3) combine splits
    attn_combine<<<B_ * H_, 128>>>();

    // 4) output projection: [128,2048] @ [2048,2048] + bias
    sgemm_bias<<<dim3(C_ / 32, M_ / 64), 128>>>(y, w_proj, b_proj, out, C_, C_);
}